// round 1
// baseline (speedup 1.0000x reference)
#include <cuda_runtime.h>
#include <math.h>

#define HID 128

// Precomputed per-node layer-0 partial projections.
// g_user_pre[0] = user_emb @ W0_ui[0:128]   (ui src part)
// g_user_pre[1] = user_emb @ W0_iu[128:256] (iu dst part)
// g_item_pre[0] = item_emb @ W0_ui[128:256] (ui dst part)
// g_item_pre[1] = item_emb @ W0_iu[0:128]   (iu src part)
#define NU_MAX 100000
#define NI_MAX 50000
__device__ float g_user_pre[2][(size_t)NU_MAX * HID];
__device__ float g_item_pre[2][(size_t)NI_MAX * HID];

#define ASH_LD 132                          // padded A-tile leading dim
#define SMEM_FLOATS (128*128 + 64*ASH_LD)   // Wsh + Ash
#define SMEM_BYTES  (SMEM_FLOATS*4 + 64*2*8)

__device__ __forceinline__ float elu_f(float x) {
    return x > 0.f ? x : (__expf(x) - 1.f);
}

// ---------------------------------------------------------------------------
// Precompute: out[row, 0:128] = emb[row, 0:128] @ W[0:128, 0:128]
// Block: 256 threads, 64 rows per block. W row-major [k][n].
// ---------------------------------------------------------------------------
__global__ void precompute_kernel(const float* __restrict__ emb,
                                  const float* __restrict__ W,
                                  float* __restrict__ out, int rows)
{
    extern __shared__ float smem[];
    float* Wsh = smem;                 // [128][128]
    float* Ash = smem + 128*128;       // [64][ASH_LD]
    const int tid = threadIdx.x;

    #pragma unroll
    for (int i = tid; i < 128*128/4; i += 256)
        ((float4*)Wsh)[i] = ((const float4*)W)[i];

    const int m0 = blockIdx.x * 64;
    for (int i = tid; i < 64*32; i += 256) {
        int r = i >> 5, c = i & 31;
        int row = m0 + r;
        float4 v = make_float4(0.f, 0.f, 0.f, 0.f);
        if (row < rows) v = ((const float4*)(emb + (size_t)row * HID))[c];
        float* ap = Ash + r*ASH_LD + c*4;
        ap[0] = v.x; ap[1] = v.y; ap[2] = v.z; ap[3] = v.w;
    }
    __syncthreads();

    const int tn = tid & 31, tm = tid >> 5;   // warp covers rows tm*8..tm*8+7, cols tn*4..tn*4+3
    float acc[8][4];
    #pragma unroll
    for (int r = 0; r < 8; r++) { acc[r][0]=acc[r][1]=acc[r][2]=acc[r][3]=0.f; }

    #pragma unroll 4
    for (int k = 0; k < 128; k++) {
        float4 bv = *(const float4*)(Wsh + k*128 + tn*4);
        #pragma unroll
        for (int r = 0; r < 8; r++) {
            float a = Ash[(tm*8+r)*ASH_LD + k];   // broadcast within warp
            acc[r][0] = fmaf(a, bv.x, acc[r][0]);
            acc[r][1] = fmaf(a, bv.y, acc[r][1]);
            acc[r][2] = fmaf(a, bv.z, acc[r][2]);
            acc[r][3] = fmaf(a, bv.w, acc[r][3]);
        }
    }

    #pragma unroll
    for (int r = 0; r < 8; r++) {
        int row = m0 + tm*8 + r;
        if (row < rows) {
            float4 v = make_float4(acc[r][0], acc[r][1], acc[r][2], acc[r][3]);
            *(float4*)(out + (size_t)row * HID + tn*4) = v;
        }
    }
}

// ---------------------------------------------------------------------------
// Edge kernel: per edge e:
//   h0 = elu(Psrc[src[e]] + Pdst[dst[e]] + b0)
//   h1 = elu(h0 @ W1 + b1)
//   out[e] = sigmoid(h1 . w2 + b2)
// Block: 256 threads, 64 edges.
// ---------------------------------------------------------------------------
__global__ void edge_kernel(const void* __restrict__ srcv,
                            const void* __restrict__ dstv,
                            const float* __restrict__ Psrc,
                            const float* __restrict__ Pdst,
                            const float* __restrict__ b0,
                            const float* __restrict__ W1,
                            const float* __restrict__ b1,
                            const float* __restrict__ W2,
                            const float* __restrict__ b2,
                            float* __restrict__ out, int nE)
{
    extern __shared__ float smem[];
    float* Wsh = smem;
    float* Ash = smem + 128*128;
    long long* sidx = (long long*)(smem + SMEM_FLOATS);
    const int tid = threadIdx.x;

    // Detect int64 vs int32 indices: non-negative values < 2^17, so if dtype
    // is int64 every odd 32-bit word (high half, little-endian) is zero.
    const int* swords = (const int*)srcv;
    int z = 0;
    #pragma unroll
    for (int i = 1; i < 64; i += 2) z |= swords[i];
    const bool is64 = (z == 0);

    #pragma unroll
    for (int i = tid; i < 128*128/4; i += 256)
        ((float4*)Wsh)[i] = ((const float4*)W1)[i];

    const int e0 = blockIdx.x * 64;
    if (tid < 64) {
        int e = e0 + tid;
        long long s = 0, d = 0;
        if (e < nE) {
            if (is64) { s = ((const long long*)srcv)[e]; d = ((const long long*)dstv)[e]; }
            else      { s = ((const int*)srcv)[e];       d = ((const int*)dstv)[e];       }
        }
        sidx[tid] = s; sidx[64 + tid] = d;
    }
    __syncthreads();

    // Gather + layer0 epilogue (add + elu) into A tile
    for (int i = tid; i < 64*32; i += 256) {
        int r = i >> 5, c = i & 31;
        long long s = sidx[r], d = sidx[64 + r];
        float4 u  = ((const float4*)(Psrc + (size_t)s * HID))[c];
        float4 v  = ((const float4*)(Pdst + (size_t)d * HID))[c];
        float4 bb = ((const float4*)b0)[c];
        float* ap = Ash + r*ASH_LD + c*4;
        ap[0] = elu_f(u.x + v.x + bb.x);
        ap[1] = elu_f(u.y + v.y + bb.y);
        ap[2] = elu_f(u.z + v.z + bb.z);
        ap[3] = elu_f(u.w + v.w + bb.w);
    }
    __syncthreads();

    // Layer1 GEMM: C[64,128] = Ash @ Wsh
    const int tn = tid & 31, tm = tid >> 5;
    float acc[8][4];
    #pragma unroll
    for (int r = 0; r < 8; r++) { acc[r][0]=acc[r][1]=acc[r][2]=acc[r][3]=0.f; }

    #pragma unroll 4
    for (int k = 0; k < 128; k++) {
        float4 bv = *(const float4*)(Wsh + k*128 + tn*4);
        #pragma unroll
        for (int r = 0; r < 8; r++) {
            float a = Ash[(tm*8+r)*ASH_LD + k];
            acc[r][0] = fmaf(a, bv.x, acc[r][0]);
            acc[r][1] = fmaf(a, bv.y, acc[r][1]);
            acc[r][2] = fmaf(a, bv.z, acc[r][2]);
            acc[r][3] = fmaf(a, bv.w, acc[r][3]);
        }
    }

    // Epilogue: elu(C + b1) . w2, warp-reduce over the 32 lanes (= 128 cols)
    float4 b1v = ((const float4*)b1)[tn];
    float4 w2v = ((const float4*)W2)[tn];   // W2 is [128,1] => 128 contiguous floats
    float bias2 = b2[0];

    #pragma unroll
    for (int r = 0; r < 8; r++) {
        float p = elu_f(acc[r][0] + b1v.x) * w2v.x
                + elu_f(acc[r][1] + b1v.y) * w2v.y
                + elu_f(acc[r][2] + b1v.z) * w2v.z
                + elu_f(acc[r][3] + b1v.w) * w2v.w;
        #pragma unroll
        for (int off = 16; off; off >>= 1)
            p += __shfl_xor_sync(0xffffffffu, p, off);
        if (tn == 0) {
            int e = e0 + tm*8 + r;
            if (e < nE) out[e] = 1.f / (1.f + __expf(-(p + bias2)));
        }
    }
}

// ---------------------------------------------------------------------------
extern "C" void kernel_launch(void* const* d_in, const int* in_sizes, int n_in,
                              void* d_out, int out_size)
{
    const float* user_emb = (const float*)d_in[0];
    const float* item_emb = (const float*)d_in[1];
    const void*  ui_src   = d_in[2];
    const void*  ui_dst   = d_in[3];
    const void*  iu_src   = d_in[4];
    const void*  iu_dst   = d_in[5];
    const float* W0_ui = (const float*)d_in[6];
    const float* b0_ui = (const float*)d_in[7];
    const float* W1_ui = (const float*)d_in[8];
    const float* b1_ui = (const float*)d_in[9];
    const float* W2_ui = (const float*)d_in[10];
    const float* b2_ui = (const float*)d_in[11];
    const float* W0_iu = (const float*)d_in[12];
    const float* b0_iu = (const float*)d_in[13];
    const float* W1_iu = (const float*)d_in[14];
    const float* b1_iu = (const float*)d_in[15];
    const float* W2_iu = (const float*)d_in[16];
    const float* b2_iu = (const float*)d_in[17];
    float* out = (float*)d_out;

    const int nU = in_sizes[0] / HID;
    const int nI = in_sizes[1] / HID;
    const int nE = in_sizes[2];

    cudaFuncSetAttribute(precompute_kernel,
                         cudaFuncAttributeMaxDynamicSharedMemorySize, SMEM_BYTES);
    cudaFuncSetAttribute(edge_kernel,
                         cudaFuncAttributeMaxDynamicSharedMemorySize, SMEM_BYTES);

    float *up, *ip;
    cudaGetSymbolAddress((void**)&up, g_user_pre);
    cudaGetSymbolAddress((void**)&ip, g_item_pre);
    float* U_ui = up;                              // user @ W0_ui_top
    float* U_iu = up + (size_t)NU_MAX * HID;       // user @ W0_iu_bot
    float* I_ui = ip;                              // item @ W0_ui_bot
    float* I_iu = ip + (size_t)NI_MAX * HID;       // item @ W0_iu_top

    const int ub = (nU + 63) / 64;
    const int ib = (nI + 63) / 64;
    const int eb = (nE + 63) / 64;

    precompute_kernel<<<ub, 256, SMEM_BYTES>>>(user_emb, W0_ui,           U_ui, nU);
    precompute_kernel<<<ib, 256, SMEM_BYTES>>>(item_emb, W0_ui + 128*128, I_ui, nI);
    precompute_kernel<<<ib, 256, SMEM_BYTES>>>(item_emb, W0_iu,           I_iu, nI);
    precompute_kernel<<<ub, 256, SMEM_BYTES>>>(user_emb, W0_iu + 128*128, U_iu, nU);

    edge_kernel<<<eb, 256, SMEM_BYTES>>>(ui_src, ui_dst, U_ui, I_ui,
                                         b0_ui, W1_ui, b1_ui, W2_ui, b2_ui,
                                         out, nE);
    edge_kernel<<<eb, 256, SMEM_BYTES>>>(iu_src, iu_dst, I_iu, U_iu,
                                         b0_iu, W1_iu, b1_iu, W2_iu, b2_iu,
                                         out + nE, nE);
}

// round 2
// speedup vs baseline: 2.5448x; 2.5448x over previous
#include <cuda_runtime.h>
#include <math.h>
#include <stdint.h>

#define HID 128
#define NU_MAX 100000
#define NI_MAX 50000
__device__ float g_user_pre[2][(size_t)NU_MAX * HID];
__device__ float g_item_pre[2][(size_t)NI_MAX * HID];

#define LD 132                     // padded A-tile leading dim (floats)
// SMEM layout (floats): Bsh[16384] | Ash[64*LD] | red[128] | b0sh[128] | sidx[128 ints]
#define BSH_FLOATS (128*128)
#define ASH_FLOATS (64*LD)
#define SMEM_EDGE_BYTES ((BSH_FLOATS + ASH_FLOATS + 128 + 128) * 4 + 128 * 4)
#define SMEM_PRE_BYTES  ((BSH_FLOATS + ASH_FLOATS) * 4)

__device__ __forceinline__ float elu_f(float x) {
    return x > 0.f ? x : (__expf(x) - 1.f);
}

__device__ __forceinline__ uint32_t f2tf32(float x) {
    uint32_t u;
    asm("cvt.rna.tf32.f32 %0, %1;" : "=r"(u) : "f"(x));
    return u;
}

__device__ __forceinline__ void mma_tf32(float4& d,
                                         uint32_t a0, uint32_t a1, uint32_t a2, uint32_t a3,
                                         uint32_t b0, uint32_t b1) {
    asm volatile(
        "mma.sync.aligned.m16n8k8.row.col.f32.tf32.tf32.f32 "
        "{%0,%1,%2,%3}, {%4,%5,%6,%7}, {%8,%9}, {%0,%1,%2,%3};"
        : "+f"(d.x), "+f"(d.y), "+f"(d.z), "+f"(d.w)
        : "r"(a0), "r"(a1), "r"(a2), "r"(a3), "r"(b0), "r"(b1));
}

// Pack W[128][128] (row-major, k-major rows) into mma B-fragment order:
// Bsh[ ((ks*16 + nt)*32 + lane)*2 + h ] = tf32( W[ks*8 + (lane&3) + 4h][nt*8 + (lane>>2)] )
__device__ __forceinline__ void pack_B(float* Bsh, const float* __restrict__ W, int tid) {
    for (int e = tid; e < 16384; e += 256) {
        int h  = e & 1;
        int l  = (e >> 1) & 31;
        int nt = (e >> 6) & 15;
        int ks = e >> 10;
        int k = ks * 8 + (l & 3) + 4 * h;
        int n = nt * 8 + (l >> 2);
        Bsh[e] = __uint_as_float(f2tf32(W[k * 128 + n]));
    }
}

// ---------------------------------------------------------------------------
// tf32 precompute: out[row,:] = emb[row,:] @ W   (rows x 128 @ 128 x 128)
// 256 threads, grid-stride over 64-row tiles. W packed once per block.
// ---------------------------------------------------------------------------
__global__ void precompute_tf32(const float* __restrict__ emb,
                                const float* __restrict__ W,
                                float* __restrict__ out, int rows)
{
    extern __shared__ float smem[];
    float* Bsh = smem;
    float* Ash = smem + BSH_FLOATS;
    const int tid  = threadIdx.x;
    const int lane = tid & 31, wid = tid >> 5;
    const int warp_m = wid & 3, warp_n = wid >> 2;
    const int g = lane >> 2, t = lane & 3;

    pack_B(Bsh, W, tid);
    __syncthreads();

    const int ntiles = (rows + 63) >> 6;
    for (int tile = blockIdx.x; tile < ntiles; tile += gridDim.x) {
        const int m0 = tile << 6;
        for (int i = tid; i < 64 * 32; i += 256) {
            int r = i >> 5, c = i & 31;
            int row = m0 + r;
            float4 v = make_float4(0.f, 0.f, 0.f, 0.f);
            if (row < rows) v = ((const float4*)(emb + (size_t)row * HID))[c];
            float* ap = Ash + r * LD + c * 4;
            ap[0] = __uint_as_float(f2tf32(v.x));
            ap[1] = __uint_as_float(f2tf32(v.y));
            ap[2] = __uint_as_float(f2tf32(v.z));
            ap[3] = __uint_as_float(f2tf32(v.w));
        }
        __syncthreads();

        float4 D[8];
        #pragma unroll
        for (int j = 0; j < 8; j++) D[j] = make_float4(0.f, 0.f, 0.f, 0.f);

        const float* Arow = Ash + (warp_m * 16 + g) * LD;
        #pragma unroll
        for (int ks = 0; ks < 16; ks++) {
            int k0 = ks * 8 + t;
            uint32_t a0 = __float_as_uint(Arow[k0]);
            uint32_t a1 = __float_as_uint(Arow[8 * LD + k0]);
            uint32_t a2 = __float_as_uint(Arow[k0 + 4]);
            uint32_t a3 = __float_as_uint(Arow[8 * LD + k0 + 4]);
            const float2* Bk = (const float2*)Bsh + (ks * 16 + warp_n * 8) * 32 + lane;
            #pragma unroll
            for (int j = 0; j < 8; j++) {
                float2 bb = Bk[j * 32];
                mma_tf32(D[j], a0, a1, a2, a3,
                         __float_as_uint(bb.x), __float_as_uint(bb.y));
            }
        }

        const int r_lo = m0 + warp_m * 16 + g;
        const int cbase = warp_n * 64 + 2 * t;
        #pragma unroll
        for (int j = 0; j < 8; j++) {
            int c = cbase + j * 8;
            if (r_lo < rows)
                *(float2*)(out + (size_t)r_lo * HID + c)       = make_float2(D[j].x, D[j].y);
            if (r_lo + 8 < rows)
                *(float2*)(out + (size_t)(r_lo + 8) * HID + c) = make_float2(D[j].z, D[j].w);
        }
        __syncthreads();
    }
}

// ---------------------------------------------------------------------------
// Edge kernel (tf32 mma):
//   h0 = elu(Psrc[src] + Pdst[dst] + b0); h1 = elu(h0 @ W1 + b1);
//   out = sigmoid(h1 . w2 + b2)
// 256 threads, grid-stride over 64-edge tiles. W1 packed once per block.
// ---------------------------------------------------------------------------
__global__ void edge_tf32(const void* __restrict__ srcv,
                          const void* __restrict__ dstv,
                          const float* __restrict__ Psrc,
                          const float* __restrict__ Pdst,
                          const float* __restrict__ b0,
                          const float* __restrict__ W1,
                          const float* __restrict__ b1,
                          const float* __restrict__ W2,
                          const float* __restrict__ b2,
                          float* __restrict__ out, int nE)
{
    extern __shared__ float smem[];
    float* Bsh  = smem;
    float* Ash  = smem + BSH_FLOATS;
    float* red  = Ash + ASH_FLOATS;     // [128]
    float* b0sh = red + 128;            // [128]
    int*   sidx = (int*)(b0sh + 128);   // [128]

    const int tid  = threadIdx.x;
    const int lane = tid & 31, wid = tid >> 5;
    const int warp_m = wid & 3, warp_n = wid >> 2;
    const int g = lane >> 2, t = lane & 3;

    // int64 vs int32 index dtype: values < 2^17 so int64 high words are 0.
    const int* swords = (const int*)srcv;
    int z = 0;
    #pragma unroll
    for (int i = 1; i < 64; i += 2) z |= swords[i];
    const bool is64 = (z == 0);

    pack_B(Bsh, W1, tid);
    for (int i = tid; i < 128; i += 256) b0sh[i] = b0[i];

    // Per-thread b1/w2 fragments (cols cbase + j*8, cbase+j*8+1)
    const int cbase = warp_n * 64 + 2 * t;
    float2 b1f[8], w2f[8];
    #pragma unroll
    for (int j = 0; j < 8; j++) {
        b1f[j] = ((const float2*)b1)[(cbase + j * 8) >> 1];
        w2f[j] = ((const float2*)W2)[(cbase + j * 8) >> 1];
    }
    const float bias2 = b2[0];
    __syncthreads();

    const int ntiles = (nE + 63) >> 6;
    for (int tile = blockIdx.x; tile < ntiles; tile += gridDim.x) {
        const int e0 = tile << 6;

        if (tid < 128) {
            int r = tid & 63;
            int e = e0 + r;
            const void* p = (tid < 64) ? srcv : dstv;
            int v = 0;
            if (e < nE)
                v = is64 ? (int)((const long long*)p)[e] : ((const int*)p)[e];
            sidx[tid] = v;
        }
        __syncthreads();

        // Gather + layer0 (add + elu) + tf32 convert into A tile
        #pragma unroll
        for (int i = tid; i < 64 * 32; i += 256) {
            int r = i >> 5, c = i & 31;
            int s = sidx[r], d = sidx[64 + r];
            float4 u  = ((const float4*)(Psrc + (size_t)s * HID))[c];
            float4 v  = ((const float4*)(Pdst + (size_t)d * HID))[c];
            float4 bb = ((const float4*)b0sh)[c];
            float* ap = Ash + r * LD + c * 4;
            ap[0] = __uint_as_float(f2tf32(elu_f(u.x + v.x + bb.x)));
            ap[1] = __uint_as_float(f2tf32(elu_f(u.y + v.y + bb.y)));
            ap[2] = __uint_as_float(f2tf32(elu_f(u.z + v.z + bb.z)));
            ap[3] = __uint_as_float(f2tf32(elu_f(u.w + v.w + bb.w)));
        }
        __syncthreads();

        // Layer1 GEMM on tensor cores
        float4 D[8];
        #pragma unroll
        for (int j = 0; j < 8; j++) D[j] = make_float4(0.f, 0.f, 0.f, 0.f);

        const float* Arow = Ash + (warp_m * 16 + g) * LD;
        #pragma unroll
        for (int ks = 0; ks < 16; ks++) {
            int k0 = ks * 8 + t;
            uint32_t a0 = __float_as_uint(Arow[k0]);
            uint32_t a1 = __float_as_uint(Arow[8 * LD + k0]);
            uint32_t a2 = __float_as_uint(Arow[k0 + 4]);
            uint32_t a3 = __float_as_uint(Arow[8 * LD + k0 + 4]);
            const float2* Bk = (const float2*)Bsh + (ks * 16 + warp_n * 8) * 32 + lane;
            #pragma unroll
            for (int j = 0; j < 8; j++) {
                float2 bb = Bk[j * 32];
                mma_tf32(D[j], a0, a1, a2, a3,
                         __float_as_uint(bb.x), __float_as_uint(bb.y));
            }
        }

        // Epilogue: elu(C + b1) . w2 partials, reduce 4 lanes -> red[], then 2 halves
        float plo = 0.f, phi = 0.f;
        #pragma unroll
        for (int j = 0; j < 8; j++) {
            plo += elu_f(D[j].x + b1f[j].x) * w2f[j].x
                 + elu_f(D[j].y + b1f[j].y) * w2f[j].y;
            phi += elu_f(D[j].z + b1f[j].x) * w2f[j].x
                 + elu_f(D[j].w + b1f[j].y) * w2f[j].y;
        }
        plo += __shfl_xor_sync(0xffffffffu, plo, 1);
        plo += __shfl_xor_sync(0xffffffffu, plo, 2);
        phi += __shfl_xor_sync(0xffffffffu, phi, 1);
        phi += __shfl_xor_sync(0xffffffffu, phi, 2);
        if (t == 0) {
            red[warp_n * 64 + warp_m * 16 + g]     = plo;
            red[warp_n * 64 + warp_m * 16 + g + 8] = phi;
        }
        __syncthreads();

        if (tid < 64) {
            int e = e0 + tid;
            if (e < nE) {
                float x = red[tid] + red[64 + tid] + bias2;
                out[e] = 1.f / (1.f + __expf(-x));
            }
        }
        __syncthreads();   // protect Ash/sidx/red before next iteration
    }
}

// ---------------------------------------------------------------------------
extern "C" void kernel_launch(void* const* d_in, const int* in_sizes, int n_in,
                              void* d_out, int out_size)
{
    const float* user_emb = (const float*)d_in[0];
    const float* item_emb = (const float*)d_in[1];
    const void*  ui_src   = d_in[2];
    const void*  ui_dst   = d_in[3];
    const void*  iu_src   = d_in[4];
    const void*  iu_dst   = d_in[5];
    const float* W0_ui = (const float*)d_in[6];
    const float* b0_ui = (const float*)d_in[7];
    const float* W1_ui = (const float*)d_in[8];
    const float* b1_ui = (const float*)d_in[9];
    const float* W2_ui = (const float*)d_in[10];
    const float* b2_ui = (const float*)d_in[11];
    const float* W0_iu = (const float*)d_in[12];
    const float* b0_iu = (const float*)d_in[13];
    const float* W1_iu = (const float*)d_in[14];
    const float* b1_iu = (const float*)d_in[15];
    const float* W2_iu = (const float*)d_in[16];
    const float* b2_iu = (const float*)d_in[17];
    float* out = (float*)d_out;

    const int nU = in_sizes[0] / HID;
    const int nI = in_sizes[1] / HID;
    const int nE = in_sizes[2];

    cudaFuncSetAttribute(precompute_tf32,
                         cudaFuncAttributeMaxDynamicSharedMemorySize, SMEM_PRE_BYTES);
    cudaFuncSetAttribute(edge_tf32,
                         cudaFuncAttributeMaxDynamicSharedMemorySize, SMEM_EDGE_BYTES);

    float *up, *ip;
    cudaGetSymbolAddress((void**)&up, g_user_pre);
    cudaGetSymbolAddress((void**)&ip, g_item_pre);
    float* U_ui = up;                          // user @ W0_ui[0:128]
    float* U_iu = up + (size_t)NU_MAX * HID;   // user @ W0_iu[128:256]
    float* I_ui = ip;                          // item @ W0_ui[128:256]
    float* I_iu = ip + (size_t)NI_MAX * HID;   // item @ W0_iu[0:128]

    const int GRID = 304;   // ~2 blocks/SM resident; grid-stride over tiles

    const int ubt = (nU + 63) / 64, ibt = (nI + 63) / 64;
    precompute_tf32<<<GRID < ubt ? GRID : ubt, 256, SMEM_PRE_BYTES>>>(user_emb, W0_ui,           U_ui, nU);
    precompute_tf32<<<GRID < ibt ? GRID : ibt, 256, SMEM_PRE_BYTES>>>(item_emb, W0_ui + 128*128, I_ui, nI);
    precompute_tf32<<<GRID < ibt ? GRID : ibt, 256, SMEM_PRE_BYTES>>>(item_emb, W0_iu,           I_iu, nI);
    precompute_tf32<<<GRID < ubt ? GRID : ubt, 256, SMEM_PRE_BYTES>>>(user_emb, W0_iu + 128*128, U_iu, nU);

    edge_tf32<<<GRID, 256, SMEM_EDGE_BYTES>>>(ui_src, ui_dst, U_ui, I_ui,
                                              b0_ui, W1_ui, b1_ui, W2_ui, b2_ui,
                                              out, nE);
    edge_tf32<<<GRID, 256, SMEM_EDGE_BYTES>>>(iu_src, iu_dst, I_iu, U_iu,
                                              b0_iu, W1_iu, b1_iu, W2_iu, b2_iu,
                                              out + nE, nE);
}

// round 3
// speedup vs baseline: 3.6897x; 1.4499x over previous
#include <cuda_runtime.h>
#include <cuda_fp16.h>
#include <stdint.h>
#include <math.h>

#define HID 128
#define NU_MAX 100000
#define NI_MAX 50000

// Node projections stored fp16 (halves gather traffic).
__device__ __half g_user_pre[2][(size_t)NU_MAX * HID];
__device__ __half g_item_pre[2][(size_t)NI_MAX * HID];

#define LDH 136                 // Ash leading dim in halves (pad 8)
#define BSH_H 16384             // halves per packed B (128x128)
#define ASH_H (128 * LDH)

#define SMEM_EDGE_BYTES (BSH_H*2 + ASH_H*2 + 256*4 + 128*4 + 256*4)
#define SMEM_PRE_BYTES  (BSH_H*2*2 + ASH_H*2)

__device__ __forceinline__ float elu_f(float x) {
    return x > 0.f ? x : (__expf(x) - 1.f);
}

__device__ __forceinline__ void mma_f16(float4& d, const uint32_t a[4], uint2 b) {
    asm volatile(
        "mma.sync.aligned.m16n8k16.row.col.f32.f16.f16.f32 "
        "{%0,%1,%2,%3}, {%4,%5,%6,%7}, {%8,%9}, {%0,%1,%2,%3};"
        : "+f"(d.x), "+f"(d.y), "+f"(d.z), "+f"(d.w)
        : "r"(a[0]), "r"(a[1]), "r"(a[2]), "r"(a[3]), "r"(b.x), "r"(b.y));
}

// Pack W[128][128] fp32 row-major into fp16 mma B-fragment order.
// Entry e=(ks,nt,lane): 4 halves {W[k0][n],W[k0+1][n],W[k0+8][n],W[k0+9][n]},
// k0 = ks*16+2t, n = nt*8+g.
__device__ __forceinline__ void pack_B_h(__half* Bsh, const float* __restrict__ W, int tid) {
    for (int e = tid; e < 4096; e += 256) {
        int ks = e >> 9;
        int nt = (e >> 5) & 15;
        int lane = e & 31;
        int g = lane >> 2, t = lane & 3;
        int k0 = ks * 16 + 2 * t;
        int n = nt * 8 + g;
        __half2* dst = (__half2*)(Bsh + (size_t)e * 4);
        dst[0] = __floats2half2_rn(W[k0 * 128 + n],      W[(k0 + 1) * 128 + n]);
        dst[1] = __floats2half2_rn(W[(k0 + 8) * 128 + n], W[(k0 + 9) * 128 + n]);
    }
}

// Core 128x128x128 tile mma: warp (warp_m in 0..3, warp_n in 0..1) covers
// rows warp_m*32..+31, cols warp_n*64..+63. D[m][j], m=0..1 (16-row frags), j=0..7.
__device__ __forceinline__ void mma_tile(const __half* Ash, const __half* Bsh,
                                         int warp_m, int warp_n, int lane,
                                         float4 D[2][8]) {
    const int g = lane >> 2, t = lane & 3;
    #pragma unroll
    for (int m = 0; m < 2; m++)
        #pragma unroll
        for (int j = 0; j < 8; j++) D[m][j] = make_float4(0.f, 0.f, 0.f, 0.f);

    #pragma unroll
    for (int ks = 0; ks < 8; ks++) {
        uint32_t a[2][4];
        #pragma unroll
        for (int m = 0; m < 2; m++) {
            const __half* Ar = Ash + (warp_m * 32 + m * 16 + g) * LDH + ks * 16 + 2 * t;
            a[m][0] = *(const uint32_t*)Ar;
            a[m][1] = *(const uint32_t*)(Ar + 8 * LDH);
            a[m][2] = *(const uint32_t*)(Ar + 8);
            a[m][3] = *(const uint32_t*)(Ar + 8 * LDH + 8);
        }
        const uint2* Bk = (const uint2*)Bsh + (ks * 16 + warp_n * 8) * 32 + lane;
        #pragma unroll
        for (int j = 0; j < 8; j++) {
            uint2 b = Bk[j * 32];
            mma_f16(D[0][j], a[0], b);
            mma_f16(D[1][j], a[1], b);
        }
    }
}

// ---------------------------------------------------------------------------
// Dual precompute: outA = emb @ Wa, outB = emb @ Wb (fp16 outputs).
// emb A-tile built once per 128-row tile, two mma passes.
// ---------------------------------------------------------------------------
__global__ void __launch_bounds__(256, 2)
pre_dual(const float* __restrict__ emb,
         const float* __restrict__ Wa, const float* __restrict__ Wb,
         __half* __restrict__ outA, __half* __restrict__ outB, int rows)
{
    extern __shared__ char smraw[];
    __half* BshA = (__half*)smraw;
    __half* BshB = BshA + BSH_H;
    __half* Ash  = BshB + BSH_H;

    const int tid  = threadIdx.x;
    const int lane = tid & 31, wid = tid >> 5;
    const int warp_m = wid & 3, warp_n = wid >> 2;
    const int g = lane >> 2, t = lane & 3;
    const int cbase = warp_n * 64 + 2 * t;

    pack_B_h(BshA, Wa, tid);
    pack_B_h(BshB, Wb, tid);
    __syncthreads();

    const int ntiles = (rows + 127) >> 7;
    for (int tile = blockIdx.x; tile < ntiles; tile += gridDim.x) {
        const int m0 = tile << 7;
        // Build A tile: emb fp32 -> fp16
        #pragma unroll
        for (int i = tid; i < 128 * 32; i += 256) {
            int r = i >> 5, c = i & 31;
            int row = m0 + r;
            float4 v = make_float4(0.f, 0.f, 0.f, 0.f);
            if (row < rows) v = ((const float4*)(emb + (size_t)row * HID))[c];
            __half2 hh[2];
            hh[0] = __floats2half2_rn(v.x, v.y);
            hh[1] = __floats2half2_rn(v.z, v.w);
            *(uint2*)(Ash + r * LDH + c * 4) = *(uint2*)hh;
        }
        __syncthreads();

        #pragma unroll
        for (int pass = 0; pass < 2; pass++) {
            const __half* Bsh = pass ? BshB : BshA;
            __half* outP = pass ? outB : outA;
            float4 D[2][8];
            mma_tile(Ash, Bsh, warp_m, warp_n, lane, D);
            #pragma unroll
            for (int m = 0; m < 2; m++) {
                int r0 = m0 + warp_m * 32 + m * 16 + g;
                #pragma unroll
                for (int j = 0; j < 8; j++) {
                    int c = cbase + j * 8;
                    if (r0 < rows)
                        *(__half2*)(outP + (size_t)r0 * HID + c) =
                            __floats2half2_rn(D[m][j].x, D[m][j].y);
                    if (r0 + 8 < rows)
                        *(__half2*)(outP + (size_t)(r0 + 8) * HID + c) =
                            __floats2half2_rn(D[m][j].z, D[m][j].w);
                }
            }
        }
        __syncthreads();
    }
}

// ---------------------------------------------------------------------------
// Merged edge kernel: blocks [0, G/2) -> decoder 0, [G/2, G) -> decoder 1.
// Per 128-edge tile: gather fp16 projections, h0=elu(u+v+b0) -> fp16 A tile,
// layer1 on tensor cores, fused elu + dot(w2) + sigmoid epilogue.
// ---------------------------------------------------------------------------
struct DecParams {
    const void* src;
    const void* dst;
    const __half* Psrc;
    const __half* Pdst;
    const float *b0, *W1, *b1, *W2, *b2;
    float* out;
};

__global__ void __launch_bounds__(256, 2)
edge_fp16(DecParams p0, DecParams p1, int nE)
{
    extern __shared__ char smraw[];
    __half* Bsh  = (__half*)smraw;
    __half* Ash  = Bsh + BSH_H;
    float*  red  = (float*)(Ash + ASH_H);   // [256]
    float*  b0sh = red + 256;               // [128]
    int*    sidx = (int*)(b0sh + 128);      // [256]

    const int tid  = threadIdx.x;
    const int lane = tid & 31, wid = tid >> 5;
    const int warp_m = wid & 3, warp_n = wid >> 2;
    const int g = lane >> 2, t = lane & 3;
    const int cbase = warp_n * 64 + 2 * t;

    const int half_grid = gridDim.x >> 1;
    const bool second = blockIdx.x >= half_grid;
    const DecParams p = second ? p1 : p0;
    const int bstart = blockIdx.x - (second ? half_grid : 0);

    // int64 vs int32 indices: values < 2^17, so int64 high words are all 0.
    {
        const int* sw = (const int*)p.src;
        int z = 0;
        #pragma unroll
        for (int i = 1; i < 64; i += 2) z |= sw[i];
        // stash in register
        if (z) {} // (avoid unused warn path)
        // store flag in a register var below
    }
    const int* sw = (const int*)p.src;
    int zz = 0;
    #pragma unroll
    for (int i = 1; i < 64; i += 2) zz |= sw[i];
    const bool is64 = (zz == 0);

    pack_B_h(Bsh, p.W1, tid);
    for (int i = tid; i < 128; i += 256) b0sh[i] = p.b0[i];

    float2 b1f[8], w2f[8];
    #pragma unroll
    for (int j = 0; j < 8; j++) {
        b1f[j] = ((const float2*)p.b1)[(cbase + j * 8) >> 1];
        w2f[j] = ((const float2*)p.W2)[(cbase + j * 8) >> 1];
    }
    const float bias2 = p.b2[0];
    __syncthreads();

    const int ntiles = (nE + 127) >> 7;
    for (int tile = bstart; tile < ntiles; tile += half_grid) {
        const int e0 = tile << 7;

        // indices: 128 src + 128 dst
        {
            int r = tid & 127;
            int e = e0 + r;
            const void* ip = (tid < 128) ? p.src : p.dst;
            int v = 0;
            if (e < nE)
                v = is64 ? (int)((const long long*)ip)[e] : ((const int*)ip)[e];
            sidx[tid] = v;
        }
        __syncthreads();

        // Gather fp16 projections + layer0 (add + elu) into fp16 A tile
        #pragma unroll
        for (int i = tid; i < 128 * 16; i += 256) {
            int r = i >> 4, c = i & 15;           // c: uint4 chunk (8 halves)
            int s = sidx[r], d = sidx[128 + r];
            uint4 u4 = ((const uint4*)(p.Psrc + (size_t)s * HID))[c];
            uint4 v4 = ((const uint4*)(p.Pdst + (size_t)d * HID))[c];
            const float* bb = b0sh + c * 8;
            const __half2* uh = (const __half2*)&u4;
            const __half2* vh = (const __half2*)&v4;
            __half2 hh[4];
            #pragma unroll
            for (int q = 0; q < 4; q++) {
                float2 uf = __half22float2(uh[q]);
                float2 vf = __half22float2(vh[q]);
                float x0 = elu_f(uf.x + vf.x + bb[2 * q]);
                float x1 = elu_f(uf.y + vf.y + bb[2 * q + 1]);
                hh[q] = __floats2half2_rn(x0, x1);
            }
            *(uint4*)(Ash + r * LDH + c * 8) = *(uint4*)hh;
        }
        __syncthreads();

        // Layer1 GEMM
        float4 D[2][8];
        mma_tile(Ash, Bsh, warp_m, warp_n, lane, D);

        // Epilogue: elu(C+b1).w2 partials, quad-reduce, combine halves
        #pragma unroll
        for (int m = 0; m < 2; m++) {
            float plo = 0.f, phi = 0.f;
            #pragma unroll
            for (int j = 0; j < 8; j++) {
                plo += elu_f(D[m][j].x + b1f[j].x) * w2f[j].x
                     + elu_f(D[m][j].y + b1f[j].y) * w2f[j].y;
                phi += elu_f(D[m][j].z + b1f[j].x) * w2f[j].x
                     + elu_f(D[m][j].w + b1f[j].y) * w2f[j].y;
            }
            plo += __shfl_xor_sync(0xffffffffu, plo, 1);
            plo += __shfl_xor_sync(0xffffffffu, plo, 2);
            phi += __shfl_xor_sync(0xffffffffu, phi, 1);
            phi += __shfl_xor_sync(0xffffffffu, phi, 2);
            if (t == 0) {
                int r = warp_m * 32 + m * 16 + g;
                red[warp_n * 128 + r]     = plo;
                red[warp_n * 128 + r + 8] = phi;
            }
        }
        __syncthreads();

        {
            int r = tid & 127;
            if (tid < 128) {
                int e = e0 + r;
                if (e < nE) {
                    float x = red[r] + red[128 + r] + bias2;
                    p.out[e] = 1.f / (1.f + __expf(-x));
                }
            }
        }
        __syncthreads();
    }
}

// ---------------------------------------------------------------------------
extern "C" void kernel_launch(void* const* d_in, const int* in_sizes, int n_in,
                              void* d_out, int out_size)
{
    const float* user_emb = (const float*)d_in[0];
    const float* item_emb = (const float*)d_in[1];
    const void*  ui_src   = d_in[2];
    const void*  ui_dst   = d_in[3];
    const void*  iu_src   = d_in[4];
    const void*  iu_dst   = d_in[5];
    const float* W0_ui = (const float*)d_in[6];
    const float* b0_ui = (const float*)d_in[7];
    const float* W1_ui = (const float*)d_in[8];
    const float* b1_ui = (const float*)d_in[9];
    const float* W2_ui = (const float*)d_in[10];
    const float* b2_ui = (const float*)d_in[11];
    const float* W0_iu = (const float*)d_in[12];
    const float* b0_iu = (const float*)d_in[13];
    const float* W1_iu = (const float*)d_in[14];
    const float* b1_iu = (const float*)d_in[15];
    const float* W2_iu = (const float*)d_in[16];
    const float* b2_iu = (const float*)d_in[17];
    float* out = (float*)d_out;

    const int nU = in_sizes[0] / HID;
    const int nI = in_sizes[1] / HID;
    const int nE = in_sizes[2];

    cudaFuncSetAttribute(pre_dual,
                         cudaFuncAttributeMaxDynamicSharedMemorySize, SMEM_PRE_BYTES);
    cudaFuncSetAttribute(edge_fp16,
                         cudaFuncAttributeMaxDynamicSharedMemorySize, SMEM_EDGE_BYTES);

    __half *up, *ip;
    cudaGetSymbolAddress((void**)&up, g_user_pre);
    cudaGetSymbolAddress((void**)&ip, g_item_pre);
    __half* U_ui = up;                          // user @ W0_ui[0:128]
    __half* U_iu = up + (size_t)NU_MAX * HID;   // user @ W0_iu[128:256]
    __half* I_ui = ip;                          // item @ W0_ui[128:256]
    __half* I_iu = ip + (size_t)NI_MAX * HID;   // item @ W0_iu[0:128]

    const int GRID = 296;  // 2 blocks/SM x 148

    pre_dual<<<GRID, 256, SMEM_PRE_BYTES>>>(user_emb, W0_ui, W0_iu + 128 * 128,
                                            U_ui, U_iu, nU);
    pre_dual<<<GRID, 256, SMEM_PRE_BYTES>>>(item_emb, W0_ui + 128 * 128, W0_iu,
                                            I_ui, I_iu, nI);

    DecParams p0, p1;
    p0.src = ui_src; p0.dst = ui_dst; p0.Psrc = U_ui; p0.Pdst = I_ui;
    p0.b0 = b0_ui; p0.W1 = W1_ui; p0.b1 = b1_ui; p0.W2 = W2_ui; p0.b2 = b2_ui;
    p0.out = out;
    p1.src = iu_src; p1.dst = iu_dst; p1.Psrc = I_iu; p1.Pdst = U_iu;
    p1.b0 = b0_iu; p1.W1 = W1_iu; p1.b1 = b1_iu; p1.W2 = W2_iu; p1.b2 = b2_iu;
    p1.out = out + nE;

    edge_fp16<<<GRID, 256, SMEM_EDGE_BYTES>>>(p0, p1, nE);
}